// round 6
// baseline (speedup 1.0000x reference)
#include <cuda_runtime.h>
#include <cuda_bf16.h>
#include <cstdint>
#include <math.h>

#define NB 8192
#define ND 128
#define C_ALPHA 2.0f
#define C_BETA 50.0f
#define C_BASE 0.5f
#define C_MARGIN 0.1f

// ---------------------------------------------------------------------------
// Scratch (allocation-free rule: __device__ globals)
// ---------------------------------------------------------------------------
__device__ float g_sim[(size_t)NB * NB];           // 256 MB
__device__ __nv_bfloat16 g_Ehi[(size_t)NB * ND];   // 2 MB
__device__ __nv_bfloat16 g_Elo[(size_t)NB * ND];   // 2 MB
__device__ float g_loss_sum;
__device__ int   g_valid_cnt;
__device__ unsigned g_done;

__device__ __forceinline__ uint32_t smem_u32(const void* p) {
    uint32_t a;
    asm("{ .reg .u64 t; cvta.to.shared.u64 t, %1; cvt.u32.u64 %0, t; }" : "=r"(a) : "l"(p));
    return a;
}

#define LDMATRIX_X4(r0, r1, r2, r3, addr)                                      \
    asm volatile("ldmatrix.sync.aligned.m8n8.x4.shared.b16 {%0,%1,%2,%3}, [%4];" \
                 : "=r"(r0), "=r"(r1), "=r"(r2), "=r"(r3) : "r"(addr))
#define LDMATRIX_X2(r0, r1, addr)                                              \
    asm volatile("ldmatrix.sync.aligned.m8n8.x2.shared.b16 {%0,%1}, [%2];"     \
                 : "=r"(r0), "=r"(r1) : "r"(addr))
#define MMA16816(c, a, b)                                                      \
    asm volatile("mma.sync.aligned.m16n8k16.row.col.f32.bf16.bf16.f32 "        \
                 "{%0,%1,%2,%3}, {%4,%5,%6,%7}, {%8,%9}, {%0,%1,%2,%3};"       \
                 : "+f"((c)[0]), "+f"((c)[1]), "+f"((c)[2]), "+f"((c)[3])      \
                 : "r"((a)[0]), "r"((a)[1]), "r"((a)[2]), "r"((a)[3]),         \
                   "r"((b)[0]), "r"((b)[1]))

// ---------------------------------------------------------------------------
// Kernel 0: split fp32 embeddings into bf16 hi + bf16 lo (+ reset accumulators)
// ---------------------------------------------------------------------------
__global__ __launch_bounds__(256) void split_kernel(const float* __restrict__ E) {
    int i = blockIdx.x * 256 + threadIdx.x;
    if (i == 0) { g_loss_sum = 0.0f; g_valid_cnt = 0; g_done = 0u; }
    float x = E[i];
    __nv_bfloat16 h = __float2bfloat16(x);
    g_Ehi[i] = h;
    g_Elo[i] = __float2bfloat16(x - __bfloat162float(h));
}

// ---------------------------------------------------------------------------
// Kernel 1: sim = Ehi*Ehi^T + Ehi*Elo^T + Elo*Ehi^T via mma.sync (bf16->fp32)
// 2080 triangular 128x128 tiles, each split into two 128x64 half-tiles
// (grid 4160) so SMEM fits 2 CTAs/SM and load/MMA/epilogue phases overlap
// across CTAs. Diagonal tiles reuse A smem as B. Off-diagonal halves also
// store the transposed 64x128 block (staged via SMEM).
// ---------------------------------------------------------------------------
#define PAD 8
#define LDT (ND + PAD)                    // 136 bf16 per row (272 B)
#define ROWB (LDT * 2)                    // 272 bytes per row
#define A_TILE_B (128 * ROWB)             // 34816
#define B_TILE_B (64 * ROWB)              // 17408
#define OFF_AHI 0
#define OFF_ALO (OFF_AHI + A_TILE_B)
#define OFF_BHI (OFF_ALO + A_TILE_B)      // 69632
#define OFF_BLO (OFF_BHI + B_TILE_B)      // 87040
#define GEMM_SMEM (OFF_BLO + B_TILE_B)    // 104448
#define TLD 132                           // fp32 transpose-stage row stride
#define NTILE (NB / 128)                  // 64
#define NTRI (NTILE * (NTILE + 1) / 2)    // 2080

__global__ __launch_bounds__(256, 2) void gemm_mma_kernel() {
    const int bid  = blockIdx.x;
    const int tile = bid >> 1;
    const int half = bid & 1;
    int rem = tile, by = 0;
    while (rem >= NTILE - by) { rem -= NTILE - by; by++; }
    const int bx = by + rem;

    extern __shared__ char smem[];
    const uint32_t sbase = smem_u32(smem);
    const int tid  = threadIdx.x;
    const int wid  = tid >> 5;
    const int lane = tid & 31;
    const int bm  = by * 128;
    const int bn  = bx * 128;
    const int bnh = bn + half * 64;       // this CTA's 64-col output slice
    const bool diag = (bx == by);

    // ---- A tiles: 128 rows hi+lo ----
    for (int t = tid; t < 2048; t += 256) {
        const int r = t >> 4;
        const int c = t & 15;
        const uint32_t so = (uint32_t)r * ROWB + c * 16;
        const size_t ga = (size_t)(bm + r) * ND + c * 8;
        *(uint4*)(smem + OFF_AHI + so) = *(const uint4*)(g_Ehi + ga);
        *(uint4*)(smem + OFF_ALO + so) = *(const uint4*)(g_Elo + ga);
    }
    // ---- B tiles: 64 rows hi+lo (skip for diagonal: reuse A) ----
    if (!diag) {
        for (int t = tid; t < 1024; t += 256) {
            const int r = t >> 4;
            const int c = t & 15;
            const uint32_t so = (uint32_t)r * ROWB + c * 16;
            const size_t gb = (size_t)(bnh + r) * ND + c * 8;
            *(uint4*)(smem + OFF_BHI + so) = *(const uint4*)(g_Ehi + gb);
            *(uint4*)(smem + OFF_BLO + so) = *(const uint4*)(g_Elo + gb);
        }
    }
    __syncthreads();

    const uint32_t bHi = diag ? (OFF_AHI + (uint32_t)half * 64 * ROWB) : OFF_BHI;
    const uint32_t bLo = diag ? (OFF_ALO + (uint32_t)half * 64 * ROWB) : OFF_BLO;

    const int warp_m = wid >> 2;          // 0..1 -> 64-row slab
    const int warp_n = wid & 3;           // 0..3 -> 16-col slab
    const int mbase = warp_m * 64;
    const int nbase = warp_n * 16;

    const int arow = ((lane >> 3) & 1) * 8 + (lane & 7);
    const int acol = ((lane >> 4) & 1) * 8;
    const int brow = lane & 7;
    const int bcol = ((lane >> 3) & 1) * 8;

    float acc[4][2][4];
#pragma unroll
    for (int mi = 0; mi < 4; mi++)
#pragma unroll
        for (int ni = 0; ni < 2; ni++)
#pragma unroll
            for (int q = 0; q < 4; q++) acc[mi][ni][q] = 0.0f;

    const uint32_t Abases[3] = {sbase + OFF_AHI, sbase + OFF_AHI, sbase + OFF_ALO};
    const uint32_t Bbases[3] = {sbase + bHi, sbase + bLo, sbase + bHi};

#pragma unroll 1
    for (int p = 0; p < 3; p++) {
        const uint32_t Ab = Abases[p];
        const uint32_t Bb = Bbases[p];
#pragma unroll
        for (int k0 = 0; k0 < ND; k0 += 16) {
            uint32_t a[4][4], b[2][2];
#pragma unroll
            for (int mi = 0; mi < 4; mi++) {
                uint32_t ad = Ab + ((mbase + mi * 16 + arow) * LDT + k0 + acol) * 2;
                LDMATRIX_X4(a[mi][0], a[mi][1], a[mi][2], a[mi][3], ad);
            }
#pragma unroll
            for (int ni = 0; ni < 2; ni++) {
                uint32_t bd = Bb + ((nbase + ni * 8 + brow) * LDT + k0 + bcol) * 2;
                LDMATRIX_X2(b[ni][0], b[ni][1], bd);
            }
#pragma unroll
            for (int mi = 0; mi < 4; mi++)
#pragma unroll
                for (int ni = 0; ni < 2; ni++)
                    MMA16816(acc[mi][ni], a[mi], b[ni]);
        }
    }

    // ---- direct store (rows bm.., cols bnh..bnh+63) ----
    const int g   = lane >> 2;
    const int tig = lane & 3;
#pragma unroll
    for (int mi = 0; mi < 4; mi++) {
        const size_t row0 = (size_t)(bm + mbase + mi * 16 + g);
        const size_t row1 = row0 + 8;
#pragma unroll
        for (int ni = 0; ni < 2; ni++) {
            const int col = bnh + nbase + ni * 8 + tig * 2;
            *(float2*)(g_sim + row0 * NB + col) = make_float2(acc[mi][ni][0], acc[mi][ni][1]);
            *(float2*)(g_sim + row1 * NB + col) = make_float2(acc[mi][ni][2], acc[mi][ni][3]);
        }
    }

    // ---- transposed store (rows bnh.., cols bm..bm+127), staged via SMEM ----
    if (!diag) {
        __syncthreads();               // ldmatrix reads done; reuse smem
        float* st = (float*)smem;      // [64][TLD]
#pragma unroll
        for (int mi = 0; mi < 4; mi++) {
            const int r0 = mbase + mi * 16 + g;
#pragma unroll
            for (int ni = 0; ni < 2; ni++) {
                const int c0 = nbase + ni * 8 + tig * 2;   // 0..63
                st[(c0 + 0) * TLD + r0]     = acc[mi][ni][0];
                st[(c0 + 1) * TLD + r0]     = acc[mi][ni][1];
                st[(c0 + 0) * TLD + r0 + 8] = acc[mi][ni][2];
                st[(c0 + 1) * TLD + r0 + 8] = acc[mi][ni][3];
            }
        }
        __syncthreads();
        for (int t = tid; t < 64 * 32; t += 256) {
            const int r  = t >> 5;
            const int c4 = (t & 31) * 4;
            float4 v = *(float4*)(st + r * TLD + c4);
            *(float4*)(g_sim + (size_t)(bnh + r) * NB + bm + c4) = v;
        }
    }
}

// ---------------------------------------------------------------------------
// Kernel 2: per-row mining + loss. 512 threads, 8 rows/CTA. Labels in SMEM;
// row data double-buffered in registers (prefetch row r+1 during row r).
// Last CTA (atomic ticket) finalizes the scalar output.
// validity: anyPos<=>pmin<inf, anyNeg<=>nmax>-inf, hardPos<=>psum>0,
// hardNeg<=>nsum>0 (nmax element is hard & above cutoff whenever any is).
// ---------------------------------------------------------------------------
#define RK_ROWS 8

__global__ __launch_bounds__(512, 2) void row_kernel(const int* __restrict__ labels,
                                                     float* __restrict__ out) {
    __shared__ int   slab[NB];
    __shared__ float bufA[16], bufB[16];
    __shared__ float s_a, s_b;

    const int tid  = threadIdx.x;
    const int lane = tid & 31;
    const int wid  = tid >> 5;
    const int i0   = blockIdx.x * RK_ROWS;

    for (int t = tid; t < NB / 4; t += 512)
        ((int4*)slab)[t] = ((const int4*)labels)[t];
    __syncthreads();

    float4 cur[4], nxt[4];
    {
        const float4* row4 = (const float4*)(g_sim + (size_t)i0 * NB);
#pragma unroll
        for (int q = 0; q < 4; q++) cur[q] = row4[q * 512 + tid];
    }

    for (int r = 0; r < RK_ROWS; r++) {
        const int i  = i0 + r;
        const int li = slab[i];

        // prefetch next row (clamped; row r=7 re-reads same row harmlessly)
        {
            const int inext = (r < RK_ROWS - 1) ? i + 1 : i;
            const float4* row4 = (const float4*)(g_sim + (size_t)inext * NB);
#pragma unroll
            for (int q = 0; q < 4; q++) nxt[q] = row4[q * 512 + tid];
        }

        // ---- pass 1: extrema ----
        float pmin = INFINITY, nmax = -INFINITY;
#pragma unroll
        for (int q = 0; q < 4; q++) {
            const int j0 = (q * 512 + tid) * 4;
            const float s[4] = {cur[q].x, cur[q].y, cur[q].z, cur[q].w};
#pragma unroll
            for (int e = 0; e < 4; e++) {
                if (slab[j0 + e] == li) { if (j0 + e != i) pmin = fminf(pmin, s[e]); }
                else nmax = fmaxf(nmax, s[e]);
            }
        }
#pragma unroll
        for (int o = 16; o; o >>= 1) {
            pmin = fminf(pmin, __shfl_xor_sync(0xFFFFFFFFu, pmin, o));
            nmax = fmaxf(nmax, __shfl_xor_sync(0xFFFFFFFFu, nmax, o));
        }
        if (lane == 0) { bufA[wid] = pmin; bufB[wid] = nmax; }
        __syncthreads();
        if (tid == 0) {
            float a = bufA[0], m = bufB[0];
#pragma unroll
            for (int k = 1; k < 16; k++) { a = fminf(a, bufA[k]); m = fmaxf(m, bufB[k]); }
            s_a = a; s_b = m;
        }
        __syncthreads();
        pmin = s_a;
        nmax = s_b;
        __syncthreads();

        // ---- pass 2: hard-pair sums ----
        const float nthr = nmax - 0.45f;   // skipped terms < e^-22.5 * max term
        float psum = 0.0f, nsum = 0.0f;
#pragma unroll
        for (int q = 0; q < 4; q++) {
            const int j0 = (q * 512 + tid) * 4;
            const float s[4] = {cur[q].x, cur[q].y, cur[q].z, cur[q].w};
#pragma unroll
            for (int e = 0; e < 4; e++) {
                const float sj = s[e];
                if (slab[j0 + e] == li) {
                    if (j0 + e != i && sj - C_MARGIN < nmax)
                        psum += __expf(-C_ALPHA * (sj - C_BASE));
                } else {
                    if (sj + C_MARGIN > pmin && sj > nthr)
                        nsum += __expf(C_BETA * (sj - C_BASE));
                }
            }
        }
#pragma unroll
        for (int o = 16; o; o >>= 1) {
            psum += __shfl_xor_sync(0xFFFFFFFFu, psum, o);
            nsum += __shfl_xor_sync(0xFFFFFFFFu, nsum, o);
        }
        if (lane == 0) { bufA[wid] = psum; bufB[wid] = nsum; }
        __syncthreads();
        if (tid == 0) {
            float ps = 0.0f, ns = 0.0f;
#pragma unroll
            for (int k = 0; k < 16; k++) { ps += bufA[k]; ns += bufB[k]; }
            const bool valid = (pmin < INFINITY) && (nmax > -INFINITY) &&
                               (ps > 0.0f) && (ns > 0.0f);
            if (valid) {
                atomicAdd(&g_loss_sum, log1pf(ps) / C_ALPHA + log1pf(ns) / C_BETA);
                atomicAdd(&g_valid_cnt, 1);
            }
        }
        __syncthreads();

        // rotate buffers
#pragma unroll
        for (int q = 0; q < 4; q++) cur[q] = nxt[q];
    }

    // ---- last CTA finalizes ----
    if (tid == 0) {
        __threadfence();
        const unsigned t = atomicAdd(&g_done, 1u);
        if (t == gridDim.x - 1) {
            const int nv = *((volatile int*)&g_valid_cnt);
            const float ls = *((volatile float*)&g_loss_sum);
            out[0] = ls / (float)(nv > 1 ? nv : 1);
        }
    }
}

// ---------------------------------------------------------------------------
extern "C" void kernel_launch(void* const* d_in, const int* in_sizes, int n_in,
                              void* d_out, int out_size) {
    const float* E      = (const float*)d_in[0];
    const int*   labels = (const int*)d_in[1];
    float*       out    = (float*)d_out;

    cudaFuncSetAttribute(gemm_mma_kernel, cudaFuncAttributeMaxDynamicSharedMemorySize,
                         GEMM_SMEM);

    split_kernel<<<NB * ND / 256, 256>>>(E);
    gemm_mma_kernel<<<NTRI * 2, 256, GEMM_SMEM>>>();
    row_kernel<<<NB / RK_ROWS, 512>>>(labels, out);
}